// round 1
// baseline (speedup 1.0000x reference)
#include <cuda_runtime.h>
#include <math.h>

#define T_SEQ 2048
#define BATCH 4
#define DIN   512
#define DOUT  256
#define NROWS 16384   // 2 * BATCH * T_SEQ (q rows then k rows)

// Scratch (static __device__ — no allocation)
__device__ float g_h[NROWS * DOUT];   // hidden layer output
__device__ float g_A[NROWS * DOUT];   // a-branch MLP out: rows [0,8192)=q_a, [8192,16384)=k_a
__device__ float g_B[NROWS * DOUT];   // b-branch MLP out

// ---------------------------------------------------------------------------
// MLP GEMM: C[16384, 256] = relu(X @ W + bias)
// X rows: if Xk != nullptr, rows >= 8192 come from Xk (k tensor), else Xq.
// BM=128, BN=128, BK=16; 256 threads, 8x8 per thread.
// ---------------------------------------------------------------------------
__global__ void __launch_bounds__(256) mlp_gemm_kernel(
    const float* __restrict__ Xq, const float* __restrict__ Xk,
    const float* __restrict__ W, const float* __restrict__ bias,
    float* __restrict__ C, int K)
{
    const int BM = 128, BN = 128, BK = 16;
    __shared__ float As[BK][BM + 4];
    __shared__ float Bs[BK][BN + 4];

    int bm = blockIdx.y, bn = blockIdx.x;
    int tid = threadIdx.x;
    long rbase = (long)bm * BM;

    const float* X;
    if (Xk != nullptr && rbase >= 8192) X = Xk + (rbase - 8192) * (long)K;
    else                                X = Xq + rbase * (long)K;

    float acc[8][8];
#pragma unroll
    for (int i = 0; i < 8; i++)
#pragma unroll
        for (int j = 0; j < 8; j++) acc[i][j] = 0.f;

    int tm = tid >> 4, tn = tid & 15;

    for (int k0 = 0; k0 < K; k0 += BK) {
        // load A tile (128 rows x 16 k), transposed into As[k][m]
#pragma unroll
        for (int i = 0; i < 2; i++) {
            int idx = tid + i * 256;          // 0..511
            int r   = idx >> 2;               // row 0..127
            int kk  = (idx & 3) * 4;          // 0,4,8,12
            float4 v = *(const float4*)(X + (long)r * K + k0 + kk);
            As[kk + 0][r] = v.x; As[kk + 1][r] = v.y;
            As[kk + 2][r] = v.z; As[kk + 3][r] = v.w;
        }
        // load B tile (16 k-rows x 128 cols)
#pragma unroll
        for (int i = 0; i < 2; i++) {
            int idx = tid + i * 256;
            int r   = idx >> 5;               // 0..15
            int c   = (idx & 31) * 4;         // 0..124
            *(float4*)&Bs[r][c] =
                *(const float4*)(W + (long)(k0 + r) * DOUT + bn * BN + c);
        }
        __syncthreads();

#pragma unroll
        for (int kk = 0; kk < BK; kk++) {
            float4 a0 = *(const float4*)&As[kk][tm * 8];
            float4 a1 = *(const float4*)&As[kk][tm * 8 + 4];
            float4 b0 = *(const float4*)&Bs[kk][tn * 8];
            float4 b1 = *(const float4*)&Bs[kk][tn * 8 + 4];
            float af[8] = {a0.x,a0.y,a0.z,a0.w,a1.x,a1.y,a1.z,a1.w};
            float bf[8] = {b0.x,b0.y,b0.z,b0.w,b1.x,b1.y,b1.z,b1.w};
#pragma unroll
            for (int i = 0; i < 8; i++)
#pragma unroll
                for (int j = 0; j < 8; j++)
                    acc[i][j] = fmaf(af[i], bf[j], acc[i][j]);
        }
        __syncthreads();
    }

    float bv[8];
#pragma unroll
    for (int j = 0; j < 8; j++) bv[j] = bias[bn * BN + tn * 8 + j];
#pragma unroll
    for (int i = 0; i < 8; i++) {
        long r = rbase + tm * 8 + i;
        float o[8];
#pragma unroll
        for (int j = 0; j < 8; j++) o[j] = fmaxf(acc[i][j] + bv[j], 0.f);
        float4* dst = (float4*)(C + r * DOUT + bn * BN + tn * 8);
        dst[0] = make_float4(o[0], o[1], o[2], o[3]);
        dst[1] = make_float4(o[4], o[5], o[6], o[7]);
    }
}

// ---------------------------------------------------------------------------
// Fused score GEMM (a and b simultaneously, K=256) + HardKuma epilogue.
// 64x64 tile per block, 256 threads, 4x4 per thread per matrix.
// ---------------------------------------------------------------------------
__global__ void __launch_bounds__(256) kuma_attn_kernel(
    const float* __restrict__ A, const float* __restrict__ Bm,
    const float* __restrict__ dist_emb, float* __restrict__ out)
{
    const int BT = 64, BK = 16;
    __shared__ float QA[BK][BT + 4], KA[BK][BT + 4];
    __shared__ float QB[BK][BT + 4], KB[BK][BT + 4];
    __shared__ float sdist[23];

    int b  = blockIdx.z;
    int bt = blockIdx.y * BT;  // t (query) block
    int bs = blockIdx.x * BT;  // s (key) block
    int tid = threadIdx.x;

    if (tid < 23) sdist[tid] = dist_emb[tid];

    const float* qa = A  + ((long)b * T_SEQ + bt) * DOUT;
    const float* ka = A  + ((long)(8192 + b * T_SEQ) + bs) * DOUT;
    const float* qb = Bm + ((long)b * T_SEQ + bt) * DOUT;
    const float* kb = Bm + ((long)(8192 + b * T_SEQ) + bs) * DOUT;

    float accA[4][4], accB[4][4];
#pragma unroll
    for (int i = 0; i < 4; i++)
#pragma unroll
        for (int j = 0; j < 4; j++) { accA[i][j] = 0.f; accB[i][j] = 0.f; }

    int tm = tid >> 4, tn = tid & 15;
    int r = tid >> 2, kk4 = (tid & 3) * 4;

    for (int k0 = 0; k0 < DOUT; k0 += BK) {
        float4 va = *(const float4*)(qa + (long)r * DOUT + k0 + kk4);
        float4 vb = *(const float4*)(ka + (long)r * DOUT + k0 + kk4);
        float4 vc = *(const float4*)(qb + (long)r * DOUT + k0 + kk4);
        float4 vd = *(const float4*)(kb + (long)r * DOUT + k0 + kk4);
        QA[kk4+0][r]=va.x; QA[kk4+1][r]=va.y; QA[kk4+2][r]=va.z; QA[kk4+3][r]=va.w;
        KA[kk4+0][r]=vb.x; KA[kk4+1][r]=vb.y; KA[kk4+2][r]=vb.z; KA[kk4+3][r]=vb.w;
        QB[kk4+0][r]=vc.x; QB[kk4+1][r]=vc.y; QB[kk4+2][r]=vc.z; QB[kk4+3][r]=vc.w;
        KB[kk4+0][r]=vd.x; KB[kk4+1][r]=vd.y; KB[kk4+2][r]=vd.z; KB[kk4+3][r]=vd.w;
        __syncthreads();

#pragma unroll
        for (int kk = 0; kk < BK; kk++) {
            float4 x = *(const float4*)&QA[kk][tm * 4];
            float4 y = *(const float4*)&KA[kk][tn * 4];
            float4 u = *(const float4*)&QB[kk][tm * 4];
            float4 w = *(const float4*)&KB[kk][tn * 4];
            float xf[4] = {x.x, x.y, x.z, x.w};
            float yf[4] = {y.x, y.y, y.z, y.w};
            float uf[4] = {u.x, u.y, u.z, u.w};
            float wf[4] = {w.x, w.y, w.z, w.w};
#pragma unroll
            for (int i = 0; i < 4; i++)
#pragma unroll
                for (int j = 0; j < 4; j++) {
                    accA[i][j] = fmaf(xf[i], yf[j], accA[i][j]);
                    accB[i][j] = fmaf(uf[i], wf[j], accB[i][j]);
                }
        }
        __syncthreads();
    }

    // HardKuma epilogue
    const float LT0 = -2.48490664978800f;  // log(0.1/1.2)
    const float LT1 = -0.08701137698963f;  // log(1.1/1.2)

#pragma unroll
    for (int i = 0; i < 4; i++) {
        int t = bt + tm * 4 + i;
        float o[4];
#pragma unroll
        for (int j = 0; j < 4; j++) {
            int s = bs + tn * 4 + j;
            int rel = s - t;
            rel = max(-11, min(11, rel)) + 11;
            float rd = sdist[rel];

            float ar = accA[i][j] + rd;
            float br = accB[i][j] + rd;

            // softplus + clamp
            float a  = fmaxf(ar, 0.f) + __logf(1.f + __expf(-fabsf(ar)));
            a = fminf(fmaxf(a, 0.01f), 100.f);
            float bb = fmaxf(br, 0.f) + __logf(1.f + __expf(-fabsf(br)));
            bb = fminf(fmaxf(bb, 0.01f), 100.f);

            // p0 = 1 - (1 - t0^a)^b ; p1 = (1 - t1^a)^b
            float u0 = __expf(a * LT0);
            float u1 = __expf(a * LT1);
            float p0 = 1.f - __expf(bb * __logf(1.f - u0));
            float p1 = __expf(bb * __logf(1.f - u1));
            float pc = 1.f - p0 - p1;

            // mean = b * Beta(1 + 1/a, b), stretched + clipped
            float g  = 1.f + __fdividef(1.f, a);
            float lm = lgammaf(g) + lgammaf(bb) - lgammaf(g + bb);
            float mean = bb * __expf(lm);
            mean = fminf(fmaxf(-0.1f + 1.2f * mean, 0.f), 1.f);

            float zo = (p0 > p1) ? 0.f : 1.f;
            o[j] = (pc < 0.5f) ? zo : mean;
        }
        float4* dst = (float4*)(out + ((long)b * T_SEQ + t) * T_SEQ + bs + tn * 4);
        *dst = make_float4(o[0], o[1], o[2], o[3]);
    }
}

// ---------------------------------------------------------------------------
extern "C" void kernel_launch(void* const* d_in, const int* in_sizes, int n_in,
                              void* d_out, int out_size)
{
    const float* q    = (const float*)d_in[0];
    const float* k    = (const float*)d_in[1];
    const float* Wa1  = (const float*)d_in[2];
    const float* ba1  = (const float*)d_in[3];
    const float* Wa2  = (const float*)d_in[4];
    const float* ba2  = (const float*)d_in[5];
    const float* Wb1  = (const float*)d_in[6];
    const float* bb1  = (const float*)d_in[7];
    const float* Wb2  = (const float*)d_in[8];
    const float* bb2  = (const float*)d_in[9];
    const float* dist = (const float*)d_in[10];
    float* out = (float*)d_out;

    float *h, *A, *Bm;
    cudaGetSymbolAddress((void**)&h,  g_h);
    cudaGetSymbolAddress((void**)&A,  g_A);
    cudaGetSymbolAddress((void**)&Bm, g_B);

    dim3 blk(256);
    dim3 g1(2, 128);  // N/128, M/128
    mlp_gemm_kernel<<<g1, blk>>>(q, k, Wa1, ba1, h, DIN);       // layer1 (a)
    mlp_gemm_kernel<<<g1, blk>>>(h, nullptr, Wa2, ba2, A, DOUT); // layer2 (a)
    mlp_gemm_kernel<<<g1, blk>>>(q, k, Wb1, bb1, h, DIN);       // layer1 (b)
    mlp_gemm_kernel<<<g1, blk>>>(h, nullptr, Wb2, bb2, Bm, DOUT);// layer2 (b)

    dim3 g2(T_SEQ / 64, T_SEQ / 64, BATCH);
    kuma_attn_kernel<<<g2, blk>>>(A, Bm, dist, out);
}

// round 2
// speedup vs baseline: 1.1202x; 1.1202x over previous
#include <cuda_runtime.h>
#include <math.h>

#define T_SEQ 2048
#define BATCH 4
#define DIN   512
#define DOUT  256
#define NROWS 16384   // 2 * BATCH * T_SEQ (q rows then k rows)

// Scratch (static __device__ — no allocation)
__device__ float g_h1[NROWS * DOUT];  // hidden (a branch)
__device__ float g_h2[NROWS * DOUT];  // hidden (b branch)
__device__ float g_A[NROWS * DOUT];   // a-branch MLP out
__device__ float g_B[NROWS * DOUT];   // b-branch MLP out

// ---------------------------------------------------------------------------
// fast transcendental helpers (single MUFU each)
// ---------------------------------------------------------------------------
__device__ __forceinline__ float f_ex2(float x) {
    float y; asm("ex2.approx.ftz.f32 %0, %1;" : "=f"(y) : "f"(x)); return y;
}
__device__ __forceinline__ float f_lg2(float x) {
    float y; asm("lg2.approx.ftz.f32 %0, %1;" : "=f"(y) : "f"(x)); return y;
}
__device__ __forceinline__ float f_rcp(float x) {
    float y; asm("rcp.approx.ftz.f32 %0, %1;" : "=f"(y) : "f"(x)); return y;
}

#define LN2   0.69314718056f
#define RLN2  1.44269504089f

// ln Gamma(x), x in [0.01, 210]: shift up by 4, 2-term Stirling (err < 1e-6)
__device__ __forceinline__ float lgamma_fast(float x) {
    float p  = x * (x + 1.f) * (x + 2.f) * (x + 3.f);
    float y  = x + 4.f;
    float ly = f_lg2(y) * LN2;
    float iy = f_rcp(y);
    float c  = iy * fmaf(-0.00277777778f, iy * iy, 0.08333333333f);
    return fmaf(y - 0.5f, ly, -y) + 0.91893853320f + c - f_lg2(p) * LN2;
}

// softplus = max(x,0) + log(1 + exp(-|x|))
__device__ __forceinline__ float softplus_fast(float x) {
    float e = f_ex2(-fabsf(x) * RLN2);
    return fmaxf(x, 0.f) + f_lg2(1.f + e) * LN2;
}

// ---------------------------------------------------------------------------
// Dual MLP GEMM: two weight sets in one launch.
// grid.x = 4: bn 0-1 -> set1 (W1,b1 -> C1), bn 2-3 -> set2 (W2,b2 -> C2)
// C[16384,256] = relu(X @ W + bias). Rows >= 8192 come from Xk if non-null.
// BM=128, BN=128, BK=16; 256 threads, 8x8 per thread.
// ---------------------------------------------------------------------------
__global__ void __launch_bounds__(256) mlp_dual_kernel(
    const float* __restrict__ Xq1, const float* __restrict__ Xk1,
    const float* __restrict__ W1,  const float* __restrict__ b1, float* __restrict__ C1,
    const float* __restrict__ Xq2, const float* __restrict__ Xk2,
    const float* __restrict__ W2,  const float* __restrict__ b2, float* __restrict__ C2,
    int K)
{
    const int BM = 128, BN = 128, BK = 16;
    __shared__ float As[BK][BM + 4];
    __shared__ float Bs[BK][BN + 4];

    int bm = blockIdx.y, bng = blockIdx.x;
    int set = bng >> 1;
    int bn  = bng & 1;
    int tid = threadIdx.x;
    long rbase = (long)bm * BM;

    const float* Xq  = set ? Xq2 : Xq1;
    const float* Xk  = set ? Xk2 : Xk1;
    const float* W   = set ? W2  : W1;
    const float* bias= set ? b2  : b1;
    float*       C   = set ? C2  : C1;

    const float* X;
    if (Xk != nullptr && rbase >= 8192) X = Xk + (rbase - 8192) * (long)K;
    else                                X = Xq + rbase * (long)K;

    float acc[8][8];
#pragma unroll
    for (int i = 0; i < 8; i++)
#pragma unroll
        for (int j = 0; j < 8; j++) acc[i][j] = 0.f;

    int tm = tid >> 4, tn = tid & 15;

    for (int k0 = 0; k0 < K; k0 += BK) {
#pragma unroll
        for (int i = 0; i < 2; i++) {
            int idx = tid + i * 256;          // 0..511
            int r   = idx >> 2;               // row 0..127
            int kk  = (idx & 3) * 4;          // 0,4,8,12
            float4 v = *(const float4*)(X + (long)r * K + k0 + kk);
            As[kk + 0][r] = v.x; As[kk + 1][r] = v.y;
            As[kk + 2][r] = v.z; As[kk + 3][r] = v.w;
        }
#pragma unroll
        for (int i = 0; i < 2; i++) {
            int idx = tid + i * 256;
            int r   = idx >> 5;               // 0..15
            int c   = (idx & 31) * 4;         // 0..124
            *(float4*)&Bs[r][c] =
                *(const float4*)(W + (long)(k0 + r) * DOUT + bn * BN + c);
        }
        __syncthreads();

#pragma unroll
        for (int kk = 0; kk < BK; kk++) {
            float4 a0 = *(const float4*)&As[kk][tm * 8];
            float4 a1 = *(const float4*)&As[kk][tm * 8 + 4];
            float4 b0 = *(const float4*)&Bs[kk][tn * 8];
            float4 b1v = *(const float4*)&Bs[kk][tn * 8 + 4];
            float af[8] = {a0.x,a0.y,a0.z,a0.w,a1.x,a1.y,a1.z,a1.w};
            float bf[8] = {b0.x,b0.y,b0.z,b0.w,b1v.x,b1v.y,b1v.z,b1v.w};
#pragma unroll
            for (int i = 0; i < 8; i++)
#pragma unroll
                for (int j = 0; j < 8; j++)
                    acc[i][j] = fmaf(af[i], bf[j], acc[i][j]);
        }
        __syncthreads();
    }

    float bv[8];
#pragma unroll
    for (int j = 0; j < 8; j++) bv[j] = bias[bn * BN + tn * 8 + j];
#pragma unroll
    for (int i = 0; i < 8; i++) {
        long r = rbase + tm * 8 + i;
        float o[8];
#pragma unroll
        for (int j = 0; j < 8; j++) o[j] = fmaxf(acc[i][j] + bv[j], 0.f);
        float4* dst = (float4*)(C + r * DOUT + bn * BN + tn * 8);
        dst[0] = make_float4(o[0], o[1], o[2], o[3]);
        dst[1] = make_float4(o[4], o[5], o[6], o[7]);
    }
}

// ---------------------------------------------------------------------------
// Fused score GEMM (a and b simultaneously, K=256) + HardKuma epilogue.
// 64x64 tile per block, 256 threads, 4x4 per thread per matrix.
// ---------------------------------------------------------------------------
__global__ void __launch_bounds__(256) kuma_attn_kernel(
    const float* __restrict__ A, const float* __restrict__ Bm,
    const float* __restrict__ dist_emb, float* __restrict__ out)
{
    const int BT = 64, BK = 16;
    __shared__ float QA[BK][BT + 4], KA[BK][BT + 4];
    __shared__ float QB[BK][BT + 4], KB[BK][BT + 4];
    __shared__ float sdist[23];

    int b  = blockIdx.z;
    int bt = blockIdx.y * BT;  // t (query) block
    int bs = blockIdx.x * BT;  // s (key) block
    int tid = threadIdx.x;

    if (tid < 23) sdist[tid] = dist_emb[tid];

    const float* qa = A  + ((long)b * T_SEQ + bt) * DOUT;
    const float* ka = A  + ((long)(8192 + b * T_SEQ) + bs) * DOUT;
    const float* qb = Bm + ((long)b * T_SEQ + bt) * DOUT;
    const float* kb = Bm + ((long)(8192 + b * T_SEQ) + bs) * DOUT;

    float accA[4][4], accB[4][4];
#pragma unroll
    for (int i = 0; i < 4; i++)
#pragma unroll
        for (int j = 0; j < 4; j++) { accA[i][j] = 0.f; accB[i][j] = 0.f; }

    int tm = tid >> 4, tn = tid & 15;
    int r = tid >> 2, kk4 = (tid & 3) * 4;

    for (int k0 = 0; k0 < DOUT; k0 += BK) {
        float4 va = *(const float4*)(qa + (long)r * DOUT + k0 + kk4);
        float4 vb = *(const float4*)(ka + (long)r * DOUT + k0 + kk4);
        float4 vc = *(const float4*)(qb + (long)r * DOUT + k0 + kk4);
        float4 vd = *(const float4*)(kb + (long)r * DOUT + k0 + kk4);
        QA[kk4+0][r]=va.x; QA[kk4+1][r]=va.y; QA[kk4+2][r]=va.z; QA[kk4+3][r]=va.w;
        KA[kk4+0][r]=vb.x; KA[kk4+1][r]=vb.y; KA[kk4+2][r]=vb.z; KA[kk4+3][r]=vb.w;
        QB[kk4+0][r]=vc.x; QB[kk4+1][r]=vc.y; QB[kk4+2][r]=vc.z; QB[kk4+3][r]=vc.w;
        KB[kk4+0][r]=vd.x; KB[kk4+1][r]=vd.y; KB[kk4+2][r]=vd.z; KB[kk4+3][r]=vd.w;
        __syncthreads();

#pragma unroll
        for (int kk = 0; kk < BK; kk++) {
            float4 x = *(const float4*)&QA[kk][tm * 4];
            float4 y = *(const float4*)&KA[kk][tn * 4];
            float4 u = *(const float4*)&QB[kk][tm * 4];
            float4 w = *(const float4*)&KB[kk][tn * 4];
            float xf[4] = {x.x, x.y, x.z, x.w};
            float yf[4] = {y.x, y.y, y.z, y.w};
            float uf[4] = {u.x, u.y, u.z, u.w};
            float wf[4] = {w.x, w.y, w.z, w.w};
#pragma unroll
            for (int i = 0; i < 4; i++)
#pragma unroll
                for (int j = 0; j < 4; j++) {
                    accA[i][j] = fmaf(xf[i], yf[j], accA[i][j]);
                    accB[i][j] = fmaf(uf[i], wf[j], accB[i][j]);
                }
        }
        __syncthreads();
    }

    // -------------------- HardKuma epilogue (fast-math) --------------------
    // t0 = 1/12, t1 = 11/12 in stretched coords
    const float K_T0 = -3.58496250072f;   // log2(1/12)
    const float K_T1 = -0.12553088208f;   // log2(11/12)

#pragma unroll
    for (int i = 0; i < 4; i++) {
        int t = bt + tm * 4 + i;
        float o[4];
#pragma unroll
        for (int j = 0; j < 4; j++) {
            int s = bs + tn * 4 + j;
            int rel = s - t;
            rel = max(-11, min(11, rel)) + 11;
            float rd = sdist[rel];

            float a  = softplus_fast(accA[i][j] + rd);
            a = fminf(fmaxf(a, 0.01f), 100.f);
            float bb = softplus_fast(accB[i][j] + rd);
            bb = fminf(fmaxf(bb, 0.01f), 100.f);

            // u0 = t0^a, u1 = t1^a  (both < 1 since a > 0)
            float u0 = f_ex2(a * K_T0);
            float u1 = f_ex2(a * K_T1);
            // E0 = (1-u0)^bb = 1 - p0 ;  p1 = (1-u1)^bb
            float E0 = f_ex2(bb * f_lg2(1.f - u0));
            float p1 = f_ex2(bb * f_lg2(1.f - u1));
            float pc = E0 - p1;             // 1 - p0 - p1

            // mean = bb * Beta(1 + 1/a, bb), stretched + clipped
            float g  = 1.f + f_rcp(a);
            float lm = lgamma_fast(g) + lgamma_fast(bb) - lgamma_fast(g + bb);
            float mean = bb * f_ex2(lm * RLN2);
            mean = fminf(fmaxf(fmaf(1.2f, mean, -0.1f), 0.f), 1.f);

            float zo = (1.f - E0 > p1) ? 0.f : 1.f;   // p0 > p1 -> 0 else 1
            o[j] = (pc < 0.5f) ? zo : mean;
        }
        float4* dst = (float4*)(out + ((long)b * T_SEQ + t) * T_SEQ + bs + tn * 4);
        *dst = make_float4(o[0], o[1], o[2], o[3]);
    }
}

// ---------------------------------------------------------------------------
extern "C" void kernel_launch(void* const* d_in, const int* in_sizes, int n_in,
                              void* d_out, int out_size)
{
    const float* q    = (const float*)d_in[0];
    const float* k    = (const float*)d_in[1];
    const float* Wa1  = (const float*)d_in[2];
    const float* ba1  = (const float*)d_in[3];
    const float* Wa2  = (const float*)d_in[4];
    const float* ba2  = (const float*)d_in[5];
    const float* Wb1  = (const float*)d_in[6];
    const float* bb1  = (const float*)d_in[7];
    const float* Wb2  = (const float*)d_in[8];
    const float* bb2  = (const float*)d_in[9];
    const float* dist = (const float*)d_in[10];
    float* out = (float*)d_out;

    float *h1, *h2, *A, *Bm;
    cudaGetSymbolAddress((void**)&h1, g_h1);
    cudaGetSymbolAddress((void**)&h2, g_h2);
    cudaGetSymbolAddress((void**)&A,  g_A);
    cudaGetSymbolAddress((void**)&Bm, g_B);

    dim3 blk(256);
    dim3 g1(4, 128);  // 2 weight sets x (N/128=2), M/128=128
    // layer 1 (a and b branches fused)
    mlp_dual_kernel<<<g1, blk>>>(q, k, Wa1, ba1, h1,
                                 q, k, Wb1, bb1, h2, DIN);
    // layer 2 (a and b branches fused)
    mlp_dual_kernel<<<g1, blk>>>(h1, nullptr, Wa2, ba2, A,
                                 h2, nullptr, Wb2, bb2, Bm, DOUT);

    dim3 g2(T_SEQ / 64, T_SEQ / 64, BATCH);
    kuma_attn_kernel<<<g2, blk>>>(A, Bm, dist, out);
}

// round 3
// speedup vs baseline: 1.9399x; 1.7317x over previous
#include <cuda_runtime.h>
#include <math.h>

#define T_SEQ 2048
#define BATCH 4
#define DIN   512
#define DOUT  256
#define NROWS 16384   // 2*BATCH*T_SEQ (q rows then k rows)

// Scratch (static __device__ — no allocation)
__device__ float g_h1[NROWS * DOUT];
__device__ float g_h2[NROWS * DOUT];
__device__ float g_A[NROWS * DOUT];
__device__ float g_B[NROWS * DOUT];

// ---------------------------------------------------------------------------
// helpers
// ---------------------------------------------------------------------------
__device__ __forceinline__ float f_ex2(float x) {
    float y; asm("ex2.approx.ftz.f32 %0, %1;" : "=f"(y) : "f"(x)); return y;
}
__device__ __forceinline__ float f_lg2(float x) {
    float y; asm("lg2.approx.ftz.f32 %0, %1;" : "=f"(y) : "f"(x)); return y;
}
__device__ __forceinline__ float f_rcp(float x) {
    float y; asm("rcp.approx.ftz.f32 %0, %1;" : "=f"(y) : "f"(x)); return y;
}
__device__ __forceinline__ unsigned f2tf32(float x) {
    unsigned y; asm("cvt.rna.tf32.f32 %0, %1;" : "=r"(y) : "f"(x)); return y;
}
__device__ __forceinline__ void mma_tf32(
    float& c0, float& c1, float& c2, float& c3,
    unsigned a0, unsigned a1, unsigned a2, unsigned a3,
    unsigned b0, unsigned b1)
{
    asm("mma.sync.aligned.m16n8k8.row.col.f32.tf32.tf32.f32 "
        "{%0,%1,%2,%3}, {%4,%5,%6,%7}, {%8,%9}, {%0,%1,%2,%3};"
        : "+f"(c0), "+f"(c1), "+f"(c2), "+f"(c3)
        : "r"(a0), "r"(a1), "r"(a2), "r"(a3), "r"(b0), "r"(b1));
}

#define LN2   0.69314718056f
#define RLN2  1.44269504089f

// ln Gamma(x), x in [0.01, 210]: shift-by-4 + 2-term Stirling (err < 1e-6)
__device__ __forceinline__ float lgamma_fast(float x) {
    float p  = x * (x + 1.f) * (x + 2.f) * (x + 3.f);
    float y  = x + 4.f;
    float ly = f_lg2(y) * LN2;
    float iy = f_rcp(y);
    float c  = iy * fmaf(-0.00277777778f, iy * iy, 0.08333333333f);
    return fmaf(y - 0.5f, ly, -y) + 0.91893853320f + c - f_lg2(p) * LN2;
}
__device__ __forceinline__ float softplus_fast(float x) {
    float e = f_ex2(-fabsf(x) * RLN2);
    return fmaxf(x, 0.f) + f_lg2(1.f + e) * LN2;
}

// full HardKuma epilogue for one (ar, br) pair
__device__ __forceinline__ float kuma_out(float ar, float br) {
    const float K_T0 = -3.58496250072f;   // log2(1/12)
    const float K_T1 = -0.12553088208f;   // log2(11/12)
    float a  = fminf(fmaxf(softplus_fast(ar), 0.01f), 100.f);
    float bb = fminf(fmaxf(softplus_fast(br), 0.01f), 100.f);
    float u0 = f_ex2(a * K_T0);
    float u1 = f_ex2(a * K_T1);
    float E0 = f_ex2(bb * f_lg2(1.f - u0));  // 1 - p0
    float p1 = f_ex2(bb * f_lg2(1.f - u1));
    float pc = E0 - p1;
    float g  = 1.f + f_rcp(a);
    float lm = lgamma_fast(g) + lgamma_fast(bb) - lgamma_fast(g + bb);
    float mean = bb * f_ex2(lm * RLN2);
    mean = fminf(fmaxf(fmaf(1.2f, mean, -0.1f), 0.f), 1.f);
    float zo = (1.f - E0 > p1) ? 0.f : 1.f;
    return (pc < 0.5f) ? zo : mean;
}

// ---------------------------------------------------------------------------
// tf32 MLP GEMM: C[16384, 256] = relu(X @ W + bias), dual weight set.
// grid = (8, 128): x = set*4 + colblock; block tile 128x64, BK=32.
// 8 warps as 4(m) x 2(n): warp tile 32x32.
// ---------------------------------------------------------------------------
__global__ void __launch_bounds__(256) mlp_tf32_kernel(
    const float* __restrict__ Xq1, const float* __restrict__ Xk1,
    const float* __restrict__ W1,  const float* __restrict__ bias1, float* __restrict__ C1,
    const float* __restrict__ Xq2, const float* __restrict__ Xk2,
    const float* __restrict__ W2,  const float* __restrict__ bias2, float* __restrict__ C2,
    int K)
{
    __shared__ unsigned As[32][132];  // [k][m], transposed
    __shared__ unsigned Bs[32][68];   // [k][n]

    int set = blockIdx.x >> 2;
    int bn  = blockIdx.x & 3;         // 4 col-blocks of 64
    long rbase = (long)blockIdx.y * 128;

    const float* Xq   = set ? Xq2 : Xq1;
    const float* Xk   = set ? Xk2 : Xk1;
    const float* W    = set ? W2  : W1;
    const float* bias = set ? bias2 : bias1;
    float*       C    = set ? C2  : C1;

    const float* X;
    if (Xk != nullptr && rbase >= 8192) X = Xk + (rbase - 8192) * (long)K;
    else                                X = Xq + rbase * (long)K;

    int tid  = threadIdx.x;
    int wid  = tid >> 5, lane = tid & 31;
    int wm   = wid >> 1, wn = wid & 1;     // warp rows = wm*32, cols = wn*32
    int g    = lane >> 2, t4 = lane & 3;

    float acc[2][4][4];
#pragma unroll
    for (int mt = 0; mt < 2; mt++)
#pragma unroll
        for (int nt = 0; nt < 4; nt++)
#pragma unroll
            for (int c = 0; c < 4; c++) acc[mt][nt][c] = 0.f;

    for (int k0 = 0; k0 < K; k0 += 32) {
        // X tile: 128 rows x 32 k
#pragma unroll
        for (int it = 0; it < 4; it++) {
            int i  = tid + it * 256;       // 0..1023
            int r  = i >> 3;
            int kq = (i & 7) * 4;
            float4 v = *(const float4*)(X + (long)r * K + k0 + kq);
            As[kq+0][r] = f2tf32(v.x); As[kq+1][r] = f2tf32(v.y);
            As[kq+2][r] = f2tf32(v.z); As[kq+3][r] = f2tf32(v.w);
        }
        // W tile: 32 k x 64 n
#pragma unroll
        for (int it = 0; it < 2; it++) {
            int i  = tid + it * 256;       // 0..511
            int kk = i >> 4;
            int c  = (i & 15) * 4;
            float4 v = *(const float4*)(W + (long)(k0 + kk) * DOUT + bn * 64 + c);
            Bs[kk][c+0] = f2tf32(v.x); Bs[kk][c+1] = f2tf32(v.y);
            Bs[kk][c+2] = f2tf32(v.z); Bs[kk][c+3] = f2tf32(v.w);
        }
        __syncthreads();

#pragma unroll
        for (int k8 = 0; k8 < 4; k8++) {
            int kb = k8 * 8;
            unsigned af[2][4];
#pragma unroll
            for (int mt = 0; mt < 2; mt++) {
                int r0 = wm * 32 + mt * 16;
                af[mt][0] = As[kb + t4    ][r0 + g];
                af[mt][1] = As[kb + t4    ][r0 + g + 8];
                af[mt][2] = As[kb + t4 + 4][r0 + g];
                af[mt][3] = As[kb + t4 + 4][r0 + g + 8];
            }
#pragma unroll
            for (int nt = 0; nt < 4; nt++) {
                int c0 = wn * 32 + nt * 8;
                unsigned b0 = Bs[kb + t4    ][c0 + g];
                unsigned b1 = Bs[kb + t4 + 4][c0 + g];
#pragma unroll
                for (int mt = 0; mt < 2; mt++)
                    mma_tf32(acc[mt][nt][0], acc[mt][nt][1],
                             acc[mt][nt][2], acc[mt][nt][3],
                             af[mt][0], af[mt][1], af[mt][2], af[mt][3], b0, b1);
            }
        }
        __syncthreads();
    }

    // epilogue: bias + relu
#pragma unroll
    for (int mt = 0; mt < 2; mt++) {
#pragma unroll
        for (int rr = 0; rr < 2; rr++) {
            long row = rbase + wm * 32 + mt * 16 + g + rr * 8;
#pragma unroll
            for (int nt = 0; nt < 4; nt++) {
                int col = bn * 64 + wn * 32 + nt * 8 + t4 * 2;
                float2 o;
                o.x = fmaxf(acc[mt][nt][rr*2+0] + bias[col    ], 0.f);
                o.y = fmaxf(acc[mt][nt][rr*2+1] + bias[col + 1], 0.f);
                *(float2*)(C + row * DOUT + col) = o;
            }
        }
    }
}

// ---------------------------------------------------------------------------
// tf32 fused score GEMM (a & b) + HardKuma epilogue.
// grid = (32, 16, 4): block tile 128(t) x 64(s), BK=16, K=256.
// 8 warps as 4(m) x 2(n): warp tile 32x32 per matrix.
// ---------------------------------------------------------------------------
__global__ void __launch_bounds__(256) kuma_attn_tf32_kernel(
    const float* __restrict__ A, const float* __restrict__ Bm,
    const float* __restrict__ dist_emb, float* __restrict__ out)
{
    __shared__ unsigned QA[16][132], QB[16][132];  // [k][t-row]
    __shared__ unsigned KA[16][68],  KB[16][68];   // [k][s-col]
    __shared__ float sdist[23];

    int b  = blockIdx.z;
    int bt = blockIdx.y * 128;
    int bs = blockIdx.x * 64;
    int tid = threadIdx.x;
    if (tid < 23) sdist[tid] = dist_emb[tid];

    int wid = tid >> 5, lane = tid & 31;
    int wm  = wid >> 1, wn = wid & 1;
    int g   = lane >> 2, t4 = lane & 3;

    const float* qa = A  + ((long)b * T_SEQ + bt) * DOUT;
    const float* ka = A  + ((long)(8192 + b * T_SEQ) + bs) * DOUT;
    const float* qb = Bm + ((long)b * T_SEQ + bt) * DOUT;
    const float* kb = Bm + ((long)(8192 + b * T_SEQ) + bs) * DOUT;

    float accA[2][4][4], accB[2][4][4];
#pragma unroll
    for (int mt = 0; mt < 2; mt++)
#pragma unroll
        for (int nt = 0; nt < 4; nt++)
#pragma unroll
            for (int c = 0; c < 4; c++) { accA[mt][nt][c] = 0.f; accB[mt][nt][c] = 0.f; }

    for (int k0 = 0; k0 < DOUT; k0 += 16) {
        // Q tiles: 128 rows x 16 k, both matrices (512 float4 each)
#pragma unroll
        for (int it = 0; it < 2; it++) {
            int i  = tid + it * 256;    // 0..511
            int r  = i >> 2;
            int kq = (i & 3) * 4;
            float4 v = *(const float4*)(qa + (long)r * DOUT + k0 + kq);
            float4 u = *(const float4*)(qb + (long)r * DOUT + k0 + kq);
            QA[kq+0][r] = f2tf32(v.x); QA[kq+1][r] = f2tf32(v.y);
            QA[kq+2][r] = f2tf32(v.z); QA[kq+3][r] = f2tf32(v.w);
            QB[kq+0][r] = f2tf32(u.x); QB[kq+1][r] = f2tf32(u.y);
            QB[kq+2][r] = f2tf32(u.z); QB[kq+3][r] = f2tf32(u.w);
        }
        // K tiles: 64 rows x 16 k (256 float4 each)
        {
            int i  = tid;               // 0..255
            int r  = i >> 2;
            int kq = (i & 3) * 4;
            float4 v = *(const float4*)(ka + (long)r * DOUT + k0 + kq);
            float4 u = *(const float4*)(kb + (long)r * DOUT + k0 + kq);
            KA[kq+0][r] = f2tf32(v.x); KA[kq+1][r] = f2tf32(v.y);
            KA[kq+2][r] = f2tf32(v.z); KA[kq+3][r] = f2tf32(v.w);
            KB[kq+0][r] = f2tf32(u.x); KB[kq+1][r] = f2tf32(u.y);
            KB[kq+2][r] = f2tf32(u.z); KB[kq+3][r] = f2tf32(u.w);
        }
        __syncthreads();

#pragma unroll
        for (int k8 = 0; k8 < 2; k8++) {
            int kb8 = k8 * 8;
            unsigned aA[2][4], aB[2][4];
#pragma unroll
            for (int mt = 0; mt < 2; mt++) {
                int r0 = wm * 32 + mt * 16;
                aA[mt][0] = QA[kb8 + t4    ][r0 + g];
                aA[mt][1] = QA[kb8 + t4    ][r0 + g + 8];
                aA[mt][2] = QA[kb8 + t4 + 4][r0 + g];
                aA[mt][3] = QA[kb8 + t4 + 4][r0 + g + 8];
                aB[mt][0] = QB[kb8 + t4    ][r0 + g];
                aB[mt][1] = QB[kb8 + t4    ][r0 + g + 8];
                aB[mt][2] = QB[kb8 + t4 + 4][r0 + g];
                aB[mt][3] = QB[kb8 + t4 + 4][r0 + g + 8];
            }
#pragma unroll
            for (int nt = 0; nt < 4; nt++) {
                int c0 = wn * 32 + nt * 8;
                unsigned bA0 = KA[kb8 + t4    ][c0 + g];
                unsigned bA1 = KA[kb8 + t4 + 4][c0 + g];
                unsigned bB0 = KB[kb8 + t4    ][c0 + g];
                unsigned bB1 = KB[kb8 + t4 + 4][c0 + g];
#pragma unroll
                for (int mt = 0; mt < 2; mt++) {
                    mma_tf32(accA[mt][nt][0], accA[mt][nt][1],
                             accA[mt][nt][2], accA[mt][nt][3],
                             aA[mt][0], aA[mt][1], aA[mt][2], aA[mt][3], bA0, bA1);
                    mma_tf32(accB[mt][nt][0], accB[mt][nt][1],
                             accB[mt][nt][2], accB[mt][nt][3],
                             aB[mt][0], aB[mt][1], aB[mt][2], aB[mt][3], bB0, bB1);
                }
            }
        }
        __syncthreads();
    }

    // HardKuma epilogue + store (float2 per fragment row)
#pragma unroll
    for (int mt = 0; mt < 2; mt++) {
#pragma unroll
        for (int rr = 0; rr < 2; rr++) {
            int trow = bt + wm * 32 + mt * 16 + g + rr * 8;
#pragma unroll
            for (int nt = 0; nt < 4; nt++) {
                int scol = bs + wn * 32 + nt * 8 + t4 * 2;
                int rel0 = max(-11, min(11, scol     - trow)) + 11;
                int rel1 = max(-11, min(11, scol + 1 - trow)) + 11;
                float rd0 = sdist[rel0], rd1 = sdist[rel1];
                float2 o;
                o.x = kuma_out(accA[mt][nt][rr*2+0] + rd0, accB[mt][nt][rr*2+0] + rd0);
                o.y = kuma_out(accA[mt][nt][rr*2+1] + rd1, accB[mt][nt][rr*2+1] + rd1);
                *(float2*)(out + ((long)b * T_SEQ + trow) * T_SEQ + scol) = o;
            }
        }
    }
}

// ---------------------------------------------------------------------------
extern "C" void kernel_launch(void* const* d_in, const int* in_sizes, int n_in,
                              void* d_out, int out_size)
{
    const float* q    = (const float*)d_in[0];
    const float* k    = (const float*)d_in[1];
    const float* Wa1  = (const float*)d_in[2];
    const float* ba1  = (const float*)d_in[3];
    const float* Wa2  = (const float*)d_in[4];
    const float* ba2  = (const float*)d_in[5];
    const float* Wb1  = (const float*)d_in[6];
    const float* bb1  = (const float*)d_in[7];
    const float* Wb2  = (const float*)d_in[8];
    const float* bb2  = (const float*)d_in[9];
    const float* dist = (const float*)d_in[10];
    float* out = (float*)d_out;

    float *h1, *h2, *A, *Bm;
    cudaGetSymbolAddress((void**)&h1, g_h1);
    cudaGetSymbolAddress((void**)&h2, g_h2);
    cudaGetSymbolAddress((void**)&A,  g_A);
    cudaGetSymbolAddress((void**)&Bm, g_B);

    dim3 blk(256);
    dim3 g1(8, 128);
    mlp_tf32_kernel<<<g1, blk>>>(q, k, Wa1, ba1, h1,
                                 q, k, Wb1, bb1, h2, DIN);
    mlp_tf32_kernel<<<g1, blk>>>(h1, nullptr, Wa2, ba2, A,
                                 h2, nullptr, Wb2, bb2, Bm, DOUT);

    dim3 g2(T_SEQ / 64, T_SEQ / 128, BATCH);
    kuma_attn_tf32_kernel<<<g2, blk>>>(A, Bm, dist, out);
}